// round 12
// baseline (speedup 1.0000x reference)
#include <cuda_runtime.h>
#include <cuda_fp16.h>
#include <cstdint>

// CausalAttention B=4, S=2048, D=1024 — mma.sync fp16x2 emulated-fp32
// cp.async staging + single fp16 plane buffer -> <=128 regs -> 2 CTAs/SM.
// d_out = [ context (4*2048*1024 f32) | attn_scores (4*2048*2048 f32) ]

#define Bb 4
#define Ss 2048
#define Dd 1024
#define BSs (Bb*Ss)

__device__ float g_Q[(size_t)BSs * Dd];
__device__ float g_K[(size_t)BSs * Dd];
__device__ float g_V[(size_t)BSs * Dd];

// 128x128 tile, BK=32, 256 threads (8 warps, 64x32 warp tiles)
#define BM 128
#define BN 128
#define BK 32
#define KPAD 40                         // halves per plane row
#define PLANEH (BM * KPAD)              // 5120 halves -> 10240 B per plane
// smem layout (bytes):
//   [0, 40960)           4 fp16 planes A0|A1|B0|B1
//   [40960, 59392)       fp32 scratch A: 128 rows x 36 floats
//   [59392, 77824)       fp32 scratch B: direct 128x36 (18432B) or BT 32x132 (16896B)
#define SCRA_OFF   40960
#define SCRB_OFF   59392
#define SMEM_BYTES 77824                // sized for the LARGER (direct) B layout
#define SCRA_LD    36
#define SCRBT_LD   132

__device__ __forceinline__ uint32_t smem_u32(const void* p) {
    uint32_t a;
    asm("{ .reg .u64 t; cvta.to.shared.u64 t, %1; cvt.u32.u64 %0, t; }" : "=r"(a) : "l"(p));
    return a;
}

__device__ __forceinline__ void cp16(uint32_t dst, const void* src) {
    asm volatile("cp.async.cg.shared.global [%0], [%1], 16;" :: "r"(dst), "l"(src));
}
__device__ __forceinline__ void cp_commit() { asm volatile("cp.async.commit_group;"); }
__device__ __forceinline__ void cp_wait0()  { asm volatile("cp.async.wait_group 0;"); }

__device__ __forceinline__ void ldsm_x4(uint32_t* a, uint32_t addr) {
    asm volatile("ldmatrix.sync.aligned.m8n8.x4.shared.b16 {%0,%1,%2,%3}, [%4];"
                 : "=r"(a[0]), "=r"(a[1]), "=r"(a[2]), "=r"(a[3]) : "r"(addr));
}

__device__ __forceinline__ void mma16816(float* d, const uint32_t* a, const uint32_t* b) {
    asm volatile(
        "mma.sync.aligned.m16n8k16.row.col.f32.f16.f16.f32 "
        "{%0,%1,%2,%3}, {%4,%5,%6,%7}, {%8,%9}, {%0,%1,%2,%3};"
        : "+f"(d[0]), "+f"(d[1]), "+f"(d[2]), "+f"(d[3])
        : "r"(a[0]), "r"(a[1]), "r"(a[2]), "r"(a[3]), "r"(b[0]), "r"(b[1]));
}

__device__ __forceinline__ void split2(float v, __half& h0, __half& h1) {
    h0 = __float2half_rn(v);
    h1 = __float2half_rn(v - __half2float(h0));
}

// ---------------------------------------------------------------------------
// Core: C(128x128) += A(128xK) . B^T; fp16 planes hold A0|A1|B0(as [n][k])|B1.
// BT=false: B source [n][ldb] (k contiguous). BT=true: B source [k][ldb].
// ---------------------------------------------------------------------------
template <bool BT>
__device__ __forceinline__ void mma_gemm(__half* sm,
                                         const float* __restrict__ A, size_t lda,
                                         const float* __restrict__ B, size_t ldb,
                                         int NB, float acc[4][4][4])
{
    const int tid  = threadIdx.x;
    const int lane = tid & 31;
    const int wid  = tid >> 5;
    const int wm   = (wid & 1) * 64;
    const int wn   = (wid >> 1) * 32;

    __half* a0p = sm;
    __half* a1p = sm + PLANEH;
    __half* b0p = sm + 2 * PLANEH;
    __half* b1p = sm + 3 * PLANEH;

    const uint32_t sbase = smem_u32(sm);
    const uint32_t scrA  = sbase + SCRA_OFF;
    const uint32_t scrB  = sbase + SCRB_OFF;
    float* scrAf = (float*)((char*)sm + SCRA_OFF);
    float* scrBf = (float*)((char*)sm + SCRB_OFF);

    // convert-phase index maps
    const int rA  = tid >> 3;            // 0..31 (+32 per it)
    const int cA  = (tid & 7) * 4;
    const int ncB = tid & 127;
    const int hkB = tid >> 7;            // 0/1

    auto issue_chunk = [&](int c) {
        const size_t ko = (size_t)c * BK;
        // A: 128 rows x 8 float4
        #pragma unroll
        for (int it = 0; it < 4; it++) {
            const int idx = it * 256 + tid;
            const int r = idx >> 3, c4 = idx & 7;
            cp16(scrA + (uint32_t)(r * SCRA_LD + c4 * 4) * 4,
                 &A[(size_t)r * lda + ko + c4 * 4]);
        }
        if (!BT) {
            #pragma unroll
            for (int it = 0; it < 4; it++) {
                const int idx = it * 256 + tid;
                const int r = idx >> 3, c4 = idx & 7;
                cp16(scrB + (uint32_t)(r * SCRA_LD + c4 * 4) * 4,
                     &B[(size_t)r * ldb + ko + c4 * 4]);
            }
        } else {
            // 32 k-rows x 32 float4 of n
            #pragma unroll
            for (int it = 0; it < 4; it++) {
                const int idx = it * 256 + tid;
                const int r = idx >> 5, c4 = idx & 31;
                cp16(scrB + (uint32_t)(r * SCRBT_LD + c4 * 4) * 4,
                     &B[(ko + r) * ldb + c4 * 4]);
            }
        }
        cp_commit();
    };

    auto convert_chunk = [&]() {
        #pragma unroll
        for (int it = 0; it < 4; it++) {
            const int r = rA + it * 32;
            float4 v = *(const float4*)&scrAf[r * SCRA_LD + cA];
            const float a[4] = {v.x, v.y, v.z, v.w};
            #pragma unroll
            for (int j = 0; j < 4; j++) {
                __half h0, h1; split2(a[j], h0, h1);
                a0p[r * KPAD + cA + j] = h0; a1p[r * KPAD + cA + j] = h1;
            }
        }
        if (!BT) {
            #pragma unroll
            for (int it = 0; it < 4; it++) {
                const int r = rA + it * 32;
                float4 v = *(const float4*)&scrBf[r * SCRA_LD + cA];
                const float a[4] = {v.x, v.y, v.z, v.w};
                #pragma unroll
                for (int j = 0; j < 4; j++) {
                    __half h0, h1; split2(a[j], h0, h1);
                    b0p[r * KPAD + cA + j] = h0; b1p[r * KPAD + cA + j] = h1;
                }
            }
        } else {
            #pragma unroll
            for (int it = 0; it < 4; it++) {
                const int kr = (it * 2 + hkB) * 4;
                #pragma unroll
                for (int j = 0; j < 4; j++) {
                    __half h0, h1;
                    split2(scrBf[(kr + j) * SCRBT_LD + ncB], h0, h1);
                    b0p[ncB * KPAD + kr + j] = h0; b1p[ncB * KPAD + kr + j] = h1;
                }
            }
        }
    };

    // prologue: chunk 0
    issue_chunk(0);
    cp_wait0();
    __syncthreads();
    convert_chunk();
    __syncthreads();

    const uint32_t aB0 = smem_u32(a0p);
    const uint32_t aB1 = smem_u32(a1p);

    for (int c = 0; c < NB; c++) {
        const bool next = (c + 1 < NB);
        if (next) issue_chunk(c + 1);       // async; overlaps compute

        // ---- compute on planes ----
        #pragma unroll
        for (int ks = 0; ks < 2; ks++) {
            uint32_t afr[2][4][4];
            const int arow = wm + (lane & 15);
            const int acol = ks * 16 + (lane >> 4) * 8;
            #pragma unroll
            for (int im = 0; im < 4; im++) {
                ldsm_x4(afr[0][im], aB0 + (uint32_t)((arow + im*16)*KPAD + acol)*2);
                ldsm_x4(afr[1][im], aB1 + (uint32_t)((arow + im*16)*KPAD + acol)*2);
            }
            uint32_t bfr[2][4][2];
            const int bn = wn + (lane >> 2);
            const int bk = ks * 16 + (lane & 3) * 2;
            #pragma unroll
            for (int in_ = 0; in_ < 4; in_++) {
                const __half* p0 = b0p + (bn + in_*8)*KPAD + bk;
                const __half* p1 = b1p + (bn + in_*8)*KPAD + bk;
                bfr[0][in_][0] = *(const uint32_t*)p0;
                bfr[0][in_][1] = *(const uint32_t*)(p0 + 8);
                bfr[1][in_][0] = *(const uint32_t*)p1;
                bfr[1][in_][1] = *(const uint32_t*)(p1 + 8);
            }
            #pragma unroll
            for (int im = 0; im < 4; im++)
                #pragma unroll
                for (int in_ = 0; in_ < 4; in_++) {
                    mma16816(acc[im][in_], afr[0][im], bfr[0][in_]);  // a0*b0
                    mma16816(acc[im][in_], afr[1][im], bfr[0][in_]);  // a1*b0
                    mma16816(acc[im][in_], afr[0][im], bfr[1][in_]);  // a0*b1
                }
        }

        if (next) {
            cp_wait0();
            __syncthreads();     // cp.async data visible; compute on planes done
            convert_chunk();     // refill planes for chunk c+1
        }
        __syncthreads();
    }
}

// ---------------------------------------------------------------------------
// Kernel 1: QKV projection.
// ---------------------------------------------------------------------------
__global__ __launch_bounds__(256, 2) void qkv_mma(
    const float* __restrict__ X,
    const float* __restrict__ Wq,
    const float* __restrict__ Wk,
    const float* __restrict__ Wv)
{
    extern __shared__ __half sm[];

    const int n0g  = blockIdx.x * BN;
    const int m0   = blockIdx.y * BM;
    const int widx = n0g >> 10;
    const int col0 = n0g & 1023;

    const float* W   = (widx == 0) ? Wq : (widx == 1) ? Wk : Wv;
    float*       Out = (widx == 0) ? g_Q : (widx == 1) ? g_K : g_V;

    float acc[4][4][4] = {};
    mma_gemm<true>(sm, X + (size_t)m0 * Dd, Dd, W + col0, Dd, Dd / BK, acc);

    const int lane = threadIdx.x & 31, wid = threadIdx.x >> 5;
    const int wm = (wid & 1) * 64, wn = (wid >> 1) * 32;
    #pragma unroll
    for (int im = 0; im < 4; im++)
        #pragma unroll
        for (int in_ = 0; in_ < 4; in_++) {
            const int r0 = m0 + wm + im*16 + (lane >> 2);
            const int c0 = col0 + wn + in_*8 + (lane & 3)*2;
            float2 v0 = {acc[im][in_][0], acc[im][in_][1]};
            float2 v1 = {acc[im][in_][2], acc[im][in_][3]};
            *(float2*)&Out[(size_t)r0 * Dd + c0]       = v0;
            *(float2*)&Out[(size_t)(r0 + 8) * Dd + c0] = v1;
        }
}

// ---------------------------------------------------------------------------
// Kernel 2: scores = (Q.K^T)/32, causal masked.
// ---------------------------------------------------------------------------
__global__ __launch_bounds__(256, 2) void scores_mma(float* __restrict__ Sout)
{
    extern __shared__ __half sm[];

    const int b  = blockIdx.z;
    const int q0 = blockIdx.y * BM;
    const int k0 = blockIdx.x * BN;
    const int tid = threadIdx.x;
    float* Sb = Sout + (size_t)b * Ss * Ss;

    if (k0 > q0 + 127) {                       // fully masked tile
        const float4 z = {0.f, 0.f, 0.f, 0.f};
        for (int t = tid; t < 4096; t += 256) {
            const int r = t >> 5, c4 = (t & 31) * 4;
            *(float4*)&Sb[(size_t)(q0 + r) * Ss + k0 + c4] = z;
        }
        return;
    }

    float acc[4][4][4] = {};
    mma_gemm<false>(sm,
        g_Q + ((size_t)b * Ss + q0) * Dd, Dd,
        g_K + ((size_t)b * Ss + k0) * Dd, Dd,
        Dd / BK, acc);

    const float scale = 0.03125f;
    const int lane = tid & 31, wid = tid >> 5;
    const int wm = (wid & 1) * 64, wn = (wid >> 1) * 32;
    #pragma unroll
    for (int im = 0; im < 4; im++)
        #pragma unroll
        for (int in_ = 0; in_ < 4; in_++) {
            const int q  = q0 + wm + im*16 + (lane >> 2);
            const int kk = k0 + wn + in_*8 + (lane & 3)*2;
            float2 v0, v1;
            v0.x = (kk   <= q)     ? acc[im][in_][0] * scale : 0.f;
            v0.y = (kk+1 <= q)     ? acc[im][in_][1] * scale : 0.f;
            v1.x = (kk   <= q + 8) ? acc[im][in_][2] * scale : 0.f;
            v1.y = (kk+1 <= q + 8) ? acc[im][in_][3] * scale : 0.f;
            *(float2*)&Sb[(size_t)q * Ss + kk]       = v0;
            *(float2*)&Sb[(size_t)(q + 8) * Ss + kk] = v1;
        }
}

// ---------------------------------------------------------------------------
// Kernel 3: causal row softmax, in place.
// ---------------------------------------------------------------------------
__global__ __launch_bounds__(256) void softmax_kernel(float* __restrict__ Sc)
{
    const int row = blockIdx.x;
    const int b = row / Ss;
    const int q = row - b * Ss;
    float* r = Sc + (size_t)b * Ss * Ss + (size_t)q * Ss;
    const int len = q + 1;
    const int t = threadIdx.x;

    __shared__ float red[256];

    float vals[8];
    int n = 0;
    float m = -3.4e38f;
    for (int i = t; i < len; i += 256) { float v = r[i]; vals[n++] = v; m = fmaxf(m, v); }
    red[t] = m; __syncthreads();
    #pragma unroll
    for (int s2 = 128; s2 > 0; s2 >>= 1) {
        if (t < s2) red[t] = fmaxf(red[t], red[t + s2]);
        __syncthreads();
    }
    m = red[0]; __syncthreads();

    float sum = 0.f;
    for (int i = 0; i < n; i++) { vals[i] = __expf(vals[i] - m); sum += vals[i]; }
    red[t] = sum; __syncthreads();
    #pragma unroll
    for (int s2 = 128; s2 > 0; s2 >>= 1) {
        if (t < s2) red[t] += red[t + s2];
        __syncthreads();
    }
    const float inv = 1.0f / red[0];

    n = 0;
    for (int i = t; i < len; i += 256) r[i] = vals[n++] * inv;
}

// ---------------------------------------------------------------------------
// Kernel 4: context = P @ V  (K loop stops past diagonal q-block).
// ---------------------------------------------------------------------------
__global__ __launch_bounds__(256, 2) void context_mma(
    const float* __restrict__ P, float* __restrict__ Ctx)
{
    extern __shared__ __half sm[];

    const int b  = blockIdx.z;
    const int q0 = blockIdx.y * BM;
    const int n0 = blockIdx.x * BN;

    float acc[4][4][4] = {};
    mma_gemm<true>(sm,
        P + (size_t)b * Ss * Ss + (size_t)q0 * Ss, Ss,
        g_V + (size_t)b * Ss * Dd + n0, Dd,
        q0 / BK + 4, acc);

    float* Ob = Ctx + (size_t)b * Ss * Dd;
    const int lane = threadIdx.x & 31, wid = threadIdx.x >> 5;
    const int wm = (wid & 1) * 64, wn = (wid >> 1) * 32;
    #pragma unroll
    for (int im = 0; im < 4; im++)
        #pragma unroll
        for (int in_ = 0; in_ < 4; in_++) {
            const int r0 = q0 + wm + im*16 + (lane >> 2);
            const int c0 = n0 + wn + in_*8 + (lane & 3)*2;
            float2 v0 = {acc[im][in_][0], acc[im][in_][1]};
            float2 v1 = {acc[im][in_][2], acc[im][in_][3]};
            *(float2*)&Ob[(size_t)r0 * Dd + c0]       = v0;
            *(float2*)&Ob[(size_t)(r0 + 8) * Dd + c0] = v1;
        }
}

// ---------------------------------------------------------------------------
extern "C" void kernel_launch(void* const* d_in, const int* in_sizes, int n_in,
                              void* d_out, int out_size)
{
    const float* x  = (const float*)d_in[0];
    const float* Wq = (const float*)d_in[1];
    const float* Wk = (const float*)d_in[2];
    const float* Wv = (const float*)d_in[3];

    float* out = (float*)d_out;
    float* ctx = out;
    float* sc  = out + (size_t)Bb * Ss * Dd;

    cudaFuncSetAttribute(qkv_mma,     cudaFuncAttributeMaxDynamicSharedMemorySize, SMEM_BYTES);
    cudaFuncSetAttribute(scores_mma,  cudaFuncAttributeMaxDynamicSharedMemorySize, SMEM_BYTES);
    cudaFuncSetAttribute(context_mma, cudaFuncAttributeMaxDynamicSharedMemorySize, SMEM_BYTES);

    qkv_mma<<<dim3(3 * Dd / BN, BSs / BM), 256, SMEM_BYTES>>>(x, Wq, Wk, Wv);
    scores_mma<<<dim3(Ss / BN, Ss / BM, Bb), 256, SMEM_BYTES>>>(sc);
    softmax_kernel<<<BSs, 256>>>(sc);
    context_mma<<<dim3(Dd / BN, Ss / BM, Bb), 256, SMEM_BYTES>>>(sc, ctx);
}

// round 13
// speedup vs baseline: 1.2137x; 1.2137x over previous
#include <cuda_runtime.h>
#include <cuda_fp16.h>
#include <cstdint>

// CausalAttention B=4, S=2048, D=1024 — mma.sync fp16x2 emulated-fp32
// Round-10 pipeline (reg prefetch + double-buffered fp16 planes) at 512 threads:
// 16 warps/CTA (4x4 grid of 32x32 warp tiles), ~105 regs -> 4 warps/SMSP.
// d_out = [ context (4*2048*1024 f32) | attn_scores (4*2048*2048 f32) ]

#define Bb 4
#define Ss 2048
#define Dd 1024
#define BSs (Bb*Ss)

__device__ float g_Q[(size_t)BSs * Dd];
__device__ float g_K[(size_t)BSs * Dd];
__device__ float g_V[(size_t)BSs * Dd];

#define BM 128
#define BN 128
#define BK 32
#define NT 512
#define KPAD 40                        // halves per plane row
#define PLANEH (BM * KPAD)             // 5120 halves
#define SMEM_BYTES (2 * 4 * PLANEH * 2)   // 2 bufs x 4 planes = 81920 B

__device__ __forceinline__ uint32_t smem_u32(const void* p) {
    uint32_t a;
    asm("{ .reg .u64 t; cvta.to.shared.u64 t, %1; cvt.u32.u64 %0, t; }" : "=r"(a) : "l"(p));
    return a;
}

__device__ __forceinline__ void ldsm_x4(uint32_t* a, uint32_t addr) {
    asm volatile("ldmatrix.sync.aligned.m8n8.x4.shared.b16 {%0,%1,%2,%3}, [%4];"
                 : "=r"(a[0]), "=r"(a[1]), "=r"(a[2]), "=r"(a[3]) : "r"(addr));
}

__device__ __forceinline__ void mma16816(float* d, const uint32_t* a, const uint32_t* b) {
    asm volatile(
        "mma.sync.aligned.m16n8k16.row.col.f32.f16.f16.f32 "
        "{%0,%1,%2,%3}, {%4,%5,%6,%7}, {%8,%9}, {%0,%1,%2,%3};"
        : "+f"(d[0]), "+f"(d[1]), "+f"(d[2]), "+f"(d[3])
        : "r"(a[0]), "r"(a[1]), "r"(a[2]), "r"(a[3]), "r"(b[0]), "r"(b[1]));
}

__device__ __forceinline__ void split2(float v, __half& h0, __half& h1) {
    h0 = __float2half_rn(v);
    h1 = __float2half_rn(v - __half2float(h0));
}

// ---------------------------------------------------------------------------
// Core: C(128x128) += A(128xK) . B^T; smem fp16 planes, B as [n][k].
// BT=false: B source [n][ldb] (k contiguous). BT=true: B source [k][ldb].
// Warp (wid) tile: wm=(wid&3)*32 rows, wn=(wid>>2)*32 cols.
// acc[2][4][4]: im in {0,1} (16-row frags), in_ in 0..3 (8-col frags).
// ---------------------------------------------------------------------------
template <bool BT>
__device__ __forceinline__ void mma_gemm(__half* sm,
                                         const float* __restrict__ A, size_t lda,
                                         const float* __restrict__ B, size_t ldb,
                                         int NB, float acc[2][4][4])
{
    const int tid  = threadIdx.x;
    const int lane = tid & 31;
    const int wid  = tid >> 5;
    const int wm   = (wid & 3) * 32;
    const int wn   = (wid >> 2) * 32;

    // staging maps (512 threads)
    const int rA  = tid >> 3;            // 0..63 (+64 per it)
    const int cA  = (tid & 7) * 4;       // 0..28
    const int ncB = tid & 127;
    const int hkB = tid >> 7;            // 0..3

    float4 pfA[2];
    float4 pfBd[2];
    float  pfBt[2][4];

    auto load_chunk = [&](int c) {
        const size_t ko = (size_t)c * BK;
        #pragma unroll
        for (int it = 0; it < 2; it++)
            pfA[it] = *(const float4*)&A[(size_t)(rA + it*64) * lda + ko + cA];
        if (!BT) {
            #pragma unroll
            for (int it = 0; it < 2; it++)
                pfBd[it] = *(const float4*)&B[(size_t)(rA + it*64) * ldb + ko + cA];
        } else {
            #pragma unroll
            for (int it = 0; it < 2; it++) {
                const int kr = (it*4 + hkB) * 4;
                #pragma unroll
                for (int j = 0; j < 4; j++)
                    pfBt[it][j] = B[(ko + kr + j) * ldb + ncB];
            }
        }
    };

    auto store_chunk = [&](int buf) {
        __half* a0 = sm + (size_t)(buf*4 + 0) * PLANEH;
        __half* a1 = sm + (size_t)(buf*4 + 1) * PLANEH;
        __half* b0 = sm + (size_t)(buf*4 + 2) * PLANEH;
        __half* b1 = sm + (size_t)(buf*4 + 3) * PLANEH;
        #pragma unroll
        for (int it = 0; it < 2; it++) {
            const int r = rA + it*64;
            const float v[4] = {pfA[it].x, pfA[it].y, pfA[it].z, pfA[it].w};
            #pragma unroll
            for (int j = 0; j < 4; j++) {
                __half h0, h1; split2(v[j], h0, h1);
                a0[r*KPAD + cA + j] = h0; a1[r*KPAD + cA + j] = h1;
            }
        }
        if (!BT) {
            #pragma unroll
            for (int it = 0; it < 2; it++) {
                const int r = rA + it*64;
                const float v[4] = {pfBd[it].x, pfBd[it].y, pfBd[it].z, pfBd[it].w};
                #pragma unroll
                for (int j = 0; j < 4; j++) {
                    __half h0, h1; split2(v[j], h0, h1);
                    b0[r*KPAD + cA + j] = h0; b1[r*KPAD + cA + j] = h1;
                }
            }
        } else {
            #pragma unroll
            for (int it = 0; it < 2; it++) {
                const int kr = (it*4 + hkB) * 4;
                #pragma unroll
                for (int j = 0; j < 4; j++) {
                    __half h0, h1; split2(pfBt[it][j], h0, h1);
                    b0[ncB*KPAD + kr + j] = h0; b1[ncB*KPAD + kr + j] = h1;
                }
            }
        }
    };

    // prologue: chunk 0 into buffer 0
    load_chunk(0);
    store_chunk(0);
    __syncthreads();

    for (int c = 0; c < NB; c++) {
        const int buf = c & 1;
        const bool next = (c + 1 < NB);
        if (next) load_chunk(c + 1);          // gmem loads issue early

        // ---- compute on buf ----
        {
            __half* a0 = sm + (size_t)(buf*4 + 0) * PLANEH;
            __half* a1 = sm + (size_t)(buf*4 + 1) * PLANEH;
            __half* b0 = sm + (size_t)(buf*4 + 2) * PLANEH;
            __half* b1 = sm + (size_t)(buf*4 + 3) * PLANEH;
            const uint32_t aB0 = smem_u32(a0);
            const uint32_t aB1 = smem_u32(a1);
            #pragma unroll
            for (int ks = 0; ks < 2; ks++) {
                uint32_t afr[2][2][4];
                const int arow = wm + (lane & 15);
                const int acol = ks*16 + (lane >> 4) * 8;
                #pragma unroll
                for (int im = 0; im < 2; im++) {
                    ldsm_x4(afr[0][im], aB0 + (uint32_t)((arow + im*16)*KPAD + acol)*2);
                    ldsm_x4(afr[1][im], aB1 + (uint32_t)((arow + im*16)*KPAD + acol)*2);
                }
                uint32_t bfr[2][4][2];
                const int bn = wn + (lane >> 2);
                const int bk = ks*16 + (lane & 3)*2;
                #pragma unroll
                for (int in_ = 0; in_ < 4; in_++) {
                    const __half* p0 = b0 + (bn + in_*8)*KPAD + bk;
                    const __half* p1 = b1 + (bn + in_*8)*KPAD + bk;
                    bfr[0][in_][0] = *(const uint32_t*)p0;
                    bfr[0][in_][1] = *(const uint32_t*)(p0 + 8);
                    bfr[1][in_][0] = *(const uint32_t*)p1;
                    bfr[1][in_][1] = *(const uint32_t*)(p1 + 8);
                }
                #pragma unroll
                for (int im = 0; im < 2; im++)
                    #pragma unroll
                    for (int in_ = 0; in_ < 4; in_++) {
                        mma16816(acc[im][in_], afr[0][im], bfr[0][in_]);  // a0*b0
                        mma16816(acc[im][in_], afr[1][im], bfr[0][in_]);  // a1*b0
                        mma16816(acc[im][in_], afr[0][im], bfr[1][in_]);  // a0*b1
                    }
            }
        }

        if (next) store_chunk(buf ^ 1);
        __syncthreads();
    }
}

// ---------------------------------------------------------------------------
// Epilogue helper: per-warp 32x32 tile store.
// ---------------------------------------------------------------------------
__device__ __forceinline__ void store_tile(float* __restrict__ Out, size_t ld,
                                           int rbase, int cbase,
                                           const float acc[2][4][4])
{
    const int lane = threadIdx.x & 31;
    #pragma unroll
    for (int im = 0; im < 2; im++)
        #pragma unroll
        for (int in_ = 0; in_ < 4; in_++) {
            const int r0 = rbase + im*16 + (lane >> 2);
            const int c0 = cbase + in_*8 + (lane & 3)*2;
            float2 v0 = {acc[im][in_][0], acc[im][in_][1]};
            float2 v1 = {acc[im][in_][2], acc[im][in_][3]};
            *(float2*)&Out[(size_t)r0 * ld + c0]       = v0;
            *(float2*)&Out[(size_t)(r0 + 8) * ld + c0] = v1;
        }
}

// ---------------------------------------------------------------------------
// Kernel 1: QKV projection.
// ---------------------------------------------------------------------------
__global__ __launch_bounds__(NT) void qkv_mma(
    const float* __restrict__ X,
    const float* __restrict__ Wq,
    const float* __restrict__ Wk,
    const float* __restrict__ Wv)
{
    extern __shared__ __half sm[];

    const int n0g  = blockIdx.x * BN;
    const int m0   = blockIdx.y * BM;
    const int widx = n0g >> 10;
    const int col0 = n0g & 1023;

    const float* W   = (widx == 0) ? Wq : (widx == 1) ? Wk : Wv;
    float*       Out = (widx == 0) ? g_Q : (widx == 1) ? g_K : g_V;

    float acc[2][4][4] = {};
    mma_gemm<true>(sm, X + (size_t)m0 * Dd, Dd, W + col0, Dd, Dd / BK, acc);

    const int wid = threadIdx.x >> 5;
    store_tile(Out, Dd, m0 + (wid & 3)*32, col0 + (wid >> 2)*32, acc);
}

// ---------------------------------------------------------------------------
// Kernel 2: scores = (Q.K^T)/32, causal masked.
// ---------------------------------------------------------------------------
__global__ __launch_bounds__(NT) void scores_mma(float* __restrict__ Sout)
{
    extern __shared__ __half sm[];

    const int b  = blockIdx.z;
    const int q0 = blockIdx.y * BM;
    const int k0 = blockIdx.x * BN;
    const int tid = threadIdx.x;
    float* Sb = Sout + (size_t)b * Ss * Ss;

    if (k0 > q0 + 127) {                       // fully masked tile
        const float4 z = {0.f, 0.f, 0.f, 0.f};
        for (int t = tid; t < 4096; t += NT) {
            const int r = t >> 5, c4 = (t & 31) * 4;
            *(float4*)&Sb[(size_t)(q0 + r) * Ss + k0 + c4] = z;
        }
        return;
    }

    float acc[2][4][4] = {};
    mma_gemm<false>(sm,
        g_Q + ((size_t)b * Ss + q0) * Dd, Dd,
        g_K + ((size_t)b * Ss + k0) * Dd, Dd,
        Dd / BK, acc);

    const float scale = 0.03125f;
    const int lane = tid & 31, wid = tid >> 5;
    const int wm = (wid & 3) * 32, wn = (wid >> 2) * 32;
    #pragma unroll
    for (int im = 0; im < 2; im++)
        #pragma unroll
        for (int in_ = 0; in_ < 4; in_++) {
            const int q  = q0 + wm + im*16 + (lane >> 2);
            const int kk = k0 + wn + in_*8 + (lane & 3)*2;
            float2 v0, v1;
            v0.x = (kk   <= q)     ? acc[im][in_][0] * scale : 0.f;
            v0.y = (kk+1 <= q)     ? acc[im][in_][1] * scale : 0.f;
            v1.x = (kk   <= q + 8) ? acc[im][in_][2] * scale : 0.f;
            v1.y = (kk+1 <= q + 8) ? acc[im][in_][3] * scale : 0.f;
            *(float2*)&Sb[(size_t)q * Ss + kk]       = v0;
            *(float2*)&Sb[(size_t)(q + 8) * Ss + kk] = v1;
        }
}

// ---------------------------------------------------------------------------
// Kernel 3: causal row softmax, in place.
// ---------------------------------------------------------------------------
__global__ __launch_bounds__(256) void softmax_kernel(float* __restrict__ Sc)
{
    const int row = blockIdx.x;
    const int b = row / Ss;
    const int q = row - b * Ss;
    float* r = Sc + (size_t)b * Ss * Ss + (size_t)q * Ss;
    const int len = q + 1;
    const int t = threadIdx.x;

    __shared__ float red[256];

    float vals[8];
    int n = 0;
    float m = -3.4e38f;
    for (int i = t; i < len; i += 256) { float v = r[i]; vals[n++] = v; m = fmaxf(m, v); }
    red[t] = m; __syncthreads();
    #pragma unroll
    for (int s2 = 128; s2 > 0; s2 >>= 1) {
        if (t < s2) red[t] = fmaxf(red[t], red[t + s2]);
        __syncthreads();
    }
    m = red[0]; __syncthreads();

    float sum = 0.f;
    for (int i = 0; i < n; i++) { vals[i] = __expf(vals[i] - m); sum += vals[i]; }
    red[t] = sum; __syncthreads();
    #pragma unroll
    for (int s2 = 128; s2 > 0; s2 >>= 1) {
        if (t < s2) red[t] += red[t + s2];
        __syncthreads();
    }
    const float inv = 1.0f / red[0];

    n = 0;
    for (int i = t; i < len; i += 256) r[i] = vals[n++] * inv;
}

// ---------------------------------------------------------------------------
// Kernel 4: context = P @ V  (K loop stops past diagonal q-block).
// ---------------------------------------------------------------------------
__global__ __launch_bounds__(NT) void context_mma(
    const float* __restrict__ P, float* __restrict__ Ctx)
{
    extern __shared__ __half sm[];

    const int b  = blockIdx.z;
    const int q0 = blockIdx.y * BM;
    const int n0 = blockIdx.x * BN;

    float acc[2][4][4] = {};
    mma_gemm<true>(sm,
        P + (size_t)b * Ss * Ss + (size_t)q0 * Ss, Ss,
        g_V + (size_t)b * Ss * Dd + n0, Dd,
        q0 / BK + 4, acc);

    const int wid = threadIdx.x >> 5;
    store_tile(Ctx + (size_t)b * Ss * Dd, Dd,
               q0 + (wid & 3)*32, n0 + (wid >> 2)*32, acc);
}

// ---------------------------------------------------------------------------
extern "C" void kernel_launch(void* const* d_in, const int* in_sizes, int n_in,
                              void* d_out, int out_size)
{
    const float* x  = (const float*)d_in[0];
    const float* Wq = (const float*)d_in[1];
    const float* Wk = (const float*)d_in[2];
    const float* Wv = (const float*)d_in[3];

    float* out = (float*)d_out;
    float* ctx = out;
    float* sc  = out + (size_t)Bb * Ss * Dd;

    cudaFuncSetAttribute(qkv_mma,     cudaFuncAttributeMaxDynamicSharedMemorySize, SMEM_BYTES);
    cudaFuncSetAttribute(scores_mma,  cudaFuncAttributeMaxDynamicSharedMemorySize, SMEM_BYTES);
    cudaFuncSetAttribute(context_mma, cudaFuncAttributeMaxDynamicSharedMemorySize, SMEM_BYTES);

    qkv_mma<<<dim3(3 * Dd / BN, BSs / BM), NT, SMEM_BYTES>>>(x, Wq, Wk, Wv);
    scores_mma<<<dim3(Ss / BN, Ss / BM, Bb), NT, SMEM_BYTES>>>(sc);
    softmax_kernel<<<BSs, 256>>>(sc);
    context_mma<<<dim3(Dd / BN, Ss / BM, Bb), NT, SMEM_BYTES>>>(sc, ctx);
}